// round 4
// baseline (speedup 1.0000x reference)
#include <cuda_runtime.h>
#include <cstdint>

#define B_SZ   32768
#define IN_DIM 128
#define ACT    512
#define MAXD   1024

// ---- smem layout (float offsets). Two unified stages of 11776 floats. ----
// A-phase stage: prev[64][68] @ +0 (4352 fl), wres[64][72] @ +4352 (4608 fl)
// B-phase stage: inputs[64][36] @ +0, Wmat mt @ +2304*(1+mt) (4 mats)
#define STG_FL   11776
#define OFF_PREV 0
#define OFF_WRES 4352
#define OFF_INP  0
#define OFF_WM   2304
#define OFF_LK   (2*STG_FL)          // 23552
#define OFF_TH   (2*STG_FL + 64)
#define SM_FLOATS (2*STG_FL + 128)   // 23680
#define SMEM_BYTES (SM_FLOATS * 4)   // 94720

__device__ __forceinline__ uint32_t smem_u32(const void* p) {
    uint32_t a;
    asm("{ .reg .u64 t; cvta.to.shared.u64 t, %1; cvt.u32.u64 %0, t; }" : "=r"(a) : "l"(p));
    return a;
}
__device__ __forceinline__ void ldsm4(uint32_t r[4], uint32_t a) {
    asm volatile("ldmatrix.sync.aligned.m8n8.x4.shared.b16 {%0,%1,%2,%3}, [%4];"
        : "=r"(r[0]), "=r"(r[1]), "=r"(r[2]), "=r"(r[3]) : "r"(a));
}
__device__ __forceinline__ void mma8(float c[4], const uint32_t a[4], uint32_t b0, uint32_t b1) {
    asm volatile("mma.sync.aligned.m16n8k8.row.col.f32.tf32.tf32.f32 "
        "{%0,%1,%2,%3},{%4,%5,%6,%7},{%8,%9},{%0,%1,%2,%3};"
        : "+f"(c[0]), "+f"(c[1]), "+f"(c[2]), "+f"(c[3])
        : "r"(a[0]), "r"(a[1]), "r"(a[2]), "r"(a[3]), "r"(b0), "r"(b1));
}
// unbiased 2-piece split: hi = rna_tf32(x), lo = rna_tf32(x - hi)
__device__ __forceinline__ void split3(uint32_t x, uint32_t& hi, uint32_t& lo) {
    float xf = __uint_as_float(x);
    uint32_t h;
    asm("cvt.rna.tf32.f32 %0, %1;" : "=r"(h) : "f"(xf));
    hi = h;
    float l = xf - __uint_as_float(h);
    asm("cvt.rna.tf32.f32 %0, %1;" : "=r"(lo) : "f"(l));
}
__device__ __forceinline__ void split4(const uint32_t x[4], uint32_t h[4], uint32_t l[4]) {
    #pragma unroll
    for (int i = 0; i < 4; i++) split3(x[i], h[i], l[i]);
}
#define CP16(dst, src) asm volatile("cp.async.cg.shared.global [%0], [%1], 16;" :: "r"(dst), "l"(src))
#define CP_COMMIT()    asm volatile("cp.async.commit_group;" ::: "memory")
#define CP_WAIT1()     asm volatile("cp.async.wait_group 1;" ::: "memory")
#define CP_WAIT0()     asm volatile("cp.async.wait_group 0;" ::: "memory")

__device__ __forceinline__ float epi(float z, float gi_, float gf_, float go_,
                                     float p, float lk, float th) {
    float ig = 1.0f / (1.0f + expf(-gi_));
    float fg = 1.0f / (1.0f + expf(-gf_));
    float og = 1.0f / (1.0f + expf(-go_));
    float s = (1.0f - lk) * (fg * p) + lk * tanhf(ig * z);
    s *= og;
    return (s > th) ? (s - th) : s;
}

__global__ __launch_bounds__(256, 2)
void gser_mma2(const float* __restrict__ inputs,
               const float* __restrict__ prev,
               const float* __restrict__ Wres,
               const float* __restrict__ Win,
               const float* __restrict__ Wgate,
               const float* __restrict__ leakp,
               const float* __restrict__ thrp,
               float* __restrict__ out)
{
    const int bx  = blockIdx.x;
    const int m0  = blockIdx.y * 64;
    const int n0  = bx * 64;
    const int tid = threadIdx.x;
    const int wid  = tid >> 5;
    const int lane = tid & 31;
    const int warp_m = wid & 1;       // 2 x 32 rows
    const int warp_n = wid >> 1;      // 4 x 16 cols
    const int m0w = warp_m * 32;
    const int n0w = warp_n * 16;

    extern __shared__ float sm[];
    const uint32_t sb = smem_u32(sm);

    // zero-fill pad: out[m0:m0+64, 512+bx*64 : +64)
    {
        const float4 z4 = make_float4(0.f, 0.f, 0.f, 0.f);
        #pragma unroll
        for (int it = 0; it < 4; ++it) {
            int idx = tid + 256 * it;
            int r = idx >> 4, q = idx & 15;
            *reinterpret_cast<float4*>(out + (size_t)(m0 + r) * MAXD + ACT + bx * 64 + 4 * q) = z4;
        }
    }
    if (tid < 64) {
        sm[OFF_LK + tid] = 1.0f / (1.0f + expf(-leakp[n0 + tid]));
        sm[OFF_TH + tid] = log1pf(expf(thrp[n0 + tid]));
    }

    // ---- prefetch lambdas (all 256 threads, uniform work) ----
    auto prefA = [&](int c, int stg) {
        const uint32_t base = sb + (uint32_t)(stg * STG_FL) * 4u;
        const float* ps = prev + (size_t)m0 * MAXD + 64 * c;
        const float* ws = Wres + (size_t)(64 * c) * MAXD + n0;
        #pragma unroll
        for (int i = 0; i < 4; ++i) {
            int u = tid + 256 * i, r = u >> 4, q = u & 15;
            CP16(base + (uint32_t)(r * 68 + 4 * q) * 4u, ps + (size_t)r * MAXD + 4 * q);
        }
        #pragma unroll
        for (int i = 0; i < 4; ++i) {
            int u = tid + 256 * i, r = u >> 4, q = u & 15;
            CP16(base + (uint32_t)(OFF_WRES + r * 72 + 4 * q) * 4u, ws + (size_t)r * MAXD + 4 * q);
        }
    };
    auto prefB = [&](int c, int stg) {
        const uint32_t base = sb + (uint32_t)(stg * STG_FL) * 4u;
        const float* is = inputs + (size_t)m0 * IN_DIM + 32 * c;
        #pragma unroll
        for (int i = 0; i < 2; ++i) {
            int u = tid + 256 * i, r = u >> 3, q = u & 7;
            CP16(base + (uint32_t)(r * 36 + 4 * q) * 4u, is + (size_t)r * IN_DIM + 4 * q);
        }
        const float* wb0 = Win   + (size_t)n0 * IN_DIM + 32 * c;
        const float* wb1 = Wgate + (size_t)n0 * IN_DIM + 32 * c;
        const float* wb2 = Wgate + (size_t)(ACT + n0) * IN_DIM + 32 * c;
        const float* wb3 = Wgate + (size_t)(2 * ACT + n0) * IN_DIM + 32 * c;
        #pragma unroll
        for (int i = 0; i < 8; ++i) {
            const int mt = i >> 1;                      // compile-time per i
            const float* w = (mt == 0) ? wb0 : (mt == 1) ? wb1 : (mt == 2) ? wb2 : wb3;
            int u = (tid + 256 * i) & 511, r = u >> 3, q = u & 7;
            CP16(base + (uint32_t)(OFF_WM * (1 + mt) + r * 36 + 4 * q) * 4u, w + (size_t)r * IN_DIM + 4 * q);
        }
    };

    // accumulators
    float az[2][2][4];
    float ag[3][2][2][4];
    #pragma unroll
    for (int a = 0; a < 2; ++a)
        #pragma unroll
        for (int b = 0; b < 2; ++b)
            #pragma unroll
            for (int k = 0; k < 4; ++k) {
                az[a][b][k] = 0.f;
                ag[0][a][b][k] = 0.f; ag[1][a][b][k] = 0.f; ag[2][a][b][k] = 0.f;
            }

    // ldsm A address pieces
    const uint32_t aLaneOff68 = (uint32_t)((m0w + (lane & 15)) * 68) * 4u + ((lane >> 4) << 4);
    const uint32_t aLaneOff36 = (uint32_t)((m0w + (lane & 15)) * 36) * 4u + ((lane >> 4) << 4);
    const int bRow = n0w + (lane & 7) + ((lane >> 4) << 3);
    const uint32_t bLaneOff36 = (uint32_t)(bRow * 36) * 4u + ((lane & 8) ? 16u : 0u);
    // phase-A scalar B (K-major wres tile, stride 72): float index pieces
    const int bScalBase = OFF_WRES + n0w + (lane >> 2);
    const int bScalK    = (lane & 3);

    // ---------------- pipeline ----------------
    prefA(0, 0);
    CP_COMMIT();

    // Phase A: 8 chunks of K=64  (z += prev @ Wres)
    for (int c = 0; c < 8; ++c) {
        if (c < 7) prefA(c + 1, (c + 1) & 1); else prefB(0, 0);
        CP_COMMIT();
        CP_WAIT1();
        __syncthreads();

        const uint32_t stB = sb + (uint32_t)((c & 1) * STG_FL) * 4u;
        const int stF = (c & 1) * STG_FL;
        #pragma unroll
        for (int ks = 0; ks < 8; ++ks) {
            uint32_t ax0[4], ax1[4], ah0[4], al0[4], ah1[4], al1[4];
            ldsm4(ax0, stB + aLaneOff68 + ks * 32);
            ldsm4(ax1, stB + aLaneOff68 + (uint32_t)(16 * 68 * 4) + ks * 32);
            split4(ax0, ah0, al0);
            split4(ax1, ah1, al1);
            const int kk = ks * 8 + bScalK;
            uint32_t bh[4], bl[4];
            split3(__float_as_uint(sm[stF + bScalBase + kk * 72]),       bh[0], bl[0]);
            split3(__float_as_uint(sm[stF + bScalBase + (kk + 4) * 72]), bh[1], bl[1]);
            split3(__float_as_uint(sm[stF + bScalBase + 8 + kk * 72]),       bh[2], bl[2]);
            split3(__float_as_uint(sm[stF + bScalBase + 8 + (kk + 4) * 72]), bh[3], bl[3]);
            mma8(az[0][0], ah0, bh[0], bh[1]);
            mma8(az[0][0], ah0, bl[0], bl[1]);
            mma8(az[0][0], al0, bh[0], bh[1]);
            mma8(az[0][1], ah0, bh[2], bh[3]);
            mma8(az[0][1], ah0, bl[2], bl[3]);
            mma8(az[0][1], al0, bh[2], bh[3]);
            mma8(az[1][0], ah1, bh[0], bh[1]);
            mma8(az[1][0], ah1, bl[0], bl[1]);
            mma8(az[1][0], al1, bh[0], bh[1]);
            mma8(az[1][1], ah1, bh[2], bh[3]);
            mma8(az[1][1], ah1, bl[2], bl[3]);
            mma8(az[1][1], al1, bh[2], bh[3]);
        }
        __syncthreads();
    }

    // Phase B: 4 chunks of K=32  (z += in@Win^T; gates = in@Wgate^T)
    for (int c = 0; c < 4; ++c) {
        if (c < 3) { prefB(c + 1, (c + 1) & 1); CP_COMMIT(); CP_WAIT1(); }
        else       { CP_WAIT0(); }
        __syncthreads();

        const uint32_t stB = sb + (uint32_t)((c & 1) * STG_FL) * 4u;
        #pragma unroll
        for (int ks = 0; ks < 4; ++ks) {
            uint32_t ax0[4], ax1[4], ah0[4], al0[4], ah1[4], al1[4];
            ldsm4(ax0, stB + aLaneOff36 + ks * 32);
            ldsm4(ax1, stB + aLaneOff36 + (uint32_t)(16 * 36 * 4) + ks * 32);
            split4(ax0, ah0, al0);
            split4(ax1, ah1, al1);
            #pragma unroll
            for (int mt = 0; mt < 4; ++mt) {
                uint32_t bx[4], bh[4], bl[4];
                ldsm4(bx, stB + (uint32_t)(OFF_WM * (1 + mt)) * 4u + bLaneOff36 + ks * 32);
                split4(bx, bh, bl);
                float (*acc)[2][4] = (mt == 0) ? az : ag[mt - 1];
                mma8(acc[0][0], ah0, bh[0], bh[1]);
                mma8(acc[0][0], ah0, bl[0], bl[1]);
                mma8(acc[0][0], al0, bh[0], bh[1]);
                mma8(acc[0][1], ah0, bh[2], bh[3]);
                mma8(acc[0][1], ah0, bl[2], bl[3]);
                mma8(acc[0][1], al0, bh[2], bh[3]);
                mma8(acc[1][0], ah1, bh[0], bh[1]);
                mma8(acc[1][0], ah1, bl[0], bl[1]);
                mma8(acc[1][0], al1, bh[0], bh[1]);
                mma8(acc[1][1], ah1, bh[2], bh[3]);
                mma8(acc[1][1], ah1, bl[2], bl[3]);
                mma8(acc[1][1], al1, bh[2], bh[3]);
            }
        }
        __syncthreads();
    }

    // ---------------- epilogue (32x16 warp tile mapping) ----------------
    const int tq = lane >> 2, tr = lane & 3;
    #pragma unroll
    for (int mi = 0; mi < 2; ++mi) {
        const int mg0 = m0 + m0w + mi * 16 + tq;
        const int mg1 = mg0 + 8;
        #pragma unroll
        for (int ni = 0; ni < 2; ++ni) {
            const int cc = n0w + ni * 8 + 2 * tr;
            const int ng = n0 + cc;
            const float lk0 = sm[OFF_LK + cc], lk1 = sm[OFF_LK + cc + 1];
            const float th0 = sm[OFF_TH + cc], th1 = sm[OFF_TH + cc + 1];
            const float2 p0 = *reinterpret_cast<const float2*>(prev + (size_t)mg0 * MAXD + ng);
            const float2 p1 = *reinterpret_cast<const float2*>(prev + (size_t)mg1 * MAXD + ng);
            float2 o0, o1;
            o0.x = epi(az[mi][ni][0], ag[0][mi][ni][0], ag[1][mi][ni][0], ag[2][mi][ni][0], p0.x, lk0, th0);
            o0.y = epi(az[mi][ni][1], ag[0][mi][ni][1], ag[1][mi][ni][1], ag[2][mi][ni][1], p0.y, lk1, th1);
            o1.x = epi(az[mi][ni][2], ag[0][mi][ni][2], ag[1][mi][ni][2], ag[2][mi][ni][2], p1.x, lk0, th0);
            o1.y = epi(az[mi][ni][3], ag[0][mi][ni][3], ag[1][mi][ni][3], ag[2][mi][ni][3], p1.y, lk1, th1);
            *reinterpret_cast<float2*>(out + (size_t)mg0 * MAXD + ng) = o0;
            *reinterpret_cast<float2*>(out + (size_t)mg1 * MAXD + ng) = o1;
        }
    }
}

extern "C" void kernel_launch(void* const* d_in, const int* in_sizes, int n_in,
                              void* d_out, int out_size)
{
    const float* inputs = (const float*)d_in[0];
    const float* prev   = (const float*)d_in[1];
    const float* Wres   = (const float*)d_in[2];
    const float* Win    = (const float*)d_in[3];
    const float* Wgate  = (const float*)d_in[4];
    const float* leakp  = (const float*)d_in[5];
    const float* thrp   = (const float*)d_in[6];
    float* out = (float*)d_out;

    cudaFuncSetAttribute(gser_mma2, cudaFuncAttributeMaxDynamicSharedMemorySize, SMEM_BYTES);

    dim3 grid(8, B_SZ / 64);
    gser_mma2<<<grid, 256, SMEM_BYTES>>>(inputs, prev, Wres, Win, Wgate, leakp, thrp, out);
}

// round 5
// speedup vs baseline: 1.1669x; 1.1669x over previous
#include <cuda_runtime.h>
#include <cuda_fp16.h>
#include <cstdint>

#define B_SZ   32768
#define IN_DIM 128
#define ACT    512
#define MAXD   1024

// ---- smem byte offsets (union of phase A / phase B regions) ----
// Phase A: prev pieces [64m][72k] fp16 (stride 144B), wres pieces [64k][72n] fp16
#define PA_PREV(p)  ((p) * 9216)
#define PA_WRES(p)  (27648 + (p) * 9216)
// Phase B: inputs pieces [64m][24k] fp16 (stride 48B), weights [mt][p] [64n][24k]
#define PB_INP(p)   ((p) * 3072)
#define PB_WM(mt,p) (9216 + ((mt) * 3 + (p)) * 3072)
#define OFF_LK 55296
#define OFF_TH 55552
#define SMEM_BYTES 55808

__device__ __forceinline__ void ldsm4(uint32_t r[4], uint32_t a) {
    asm volatile("ldmatrix.sync.aligned.m8n8.x4.shared.b16 {%0,%1,%2,%3}, [%4];"
        : "=r"(r[0]), "=r"(r[1]), "=r"(r[2]), "=r"(r[3]) : "r"(a));
}
__device__ __forceinline__ void ldsm4t(uint32_t r[4], uint32_t a) {
    asm volatile("ldmatrix.sync.aligned.m8n8.x4.trans.shared.b16 {%0,%1,%2,%3}, [%4];"
        : "=r"(r[0]), "=r"(r[1]), "=r"(r[2]), "=r"(r[3]) : "r"(a));
}
__device__ __forceinline__ uint32_t smem_u32(const void* p) {
    uint32_t a;
    asm("{ .reg .u64 t; cvta.to.shared.u64 t, %1; cvt.u32.u64 %0, t; }" : "=r"(a) : "l"(p));
    return a;
}
__device__ __forceinline__ void mma16(float c[4], const uint32_t a[4], uint32_t b0, uint32_t b1) {
    asm volatile("mma.sync.aligned.m16n8k16.row.col.f32.f16.f16.f32 "
        "{%0,%1,%2,%3},{%4,%5,%6,%7},{%8,%9},{%0,%1,%2,%3};"
        : "+f"(c[0]), "+f"(c[1]), "+f"(c[2]), "+f"(c[3])
        : "r"(a[0]), "r"(a[1]), "r"(a[2]), "r"(a[3]), "r"(b0), "r"(b1));
}
// pack (lo, hi) -> half2 reg, round-to-nearest
__device__ __forceinline__ uint32_t packh2(float lo, float hi) {
    uint32_t r;
    asm("cvt.rn.f16x2.f32 %0, %1, %2;" : "=r"(r) : "f"(hi), "f"(lo));
    return r;
}
__device__ __forceinline__ float2 unph2(uint32_t p) {
    __half2 h;
    *reinterpret_cast<uint32_t*>(&h) = p;
    return __half22float2(h);
}
// 3-piece fp16 split of a pair of floats: x = h + m + l (each fp16, rn)
__device__ __forceinline__ void split_pair(float x0, float x1,
                                           uint32_t& ph, uint32_t& pm, uint32_t& pl) {
    ph = packh2(x0, x1);
    float2 h = unph2(ph);
    float r0 = x0 - h.x, r1 = x1 - h.y;
    pm = packh2(r0, r1);
    float2 m = unph2(pm);
    pl = packh2(r0 - m.x, r1 - m.y);
}
// 6-term correction product: acc += (ah+am+al)*(bh+bm+bl) to ~2^-33
__device__ __forceinline__ void six(float c[4],
                                    const uint32_t ah[4], const uint32_t am[4], const uint32_t al[4],
                                    uint32_t bh0, uint32_t bh1, uint32_t bm0, uint32_t bm1,
                                    uint32_t bl0, uint32_t bl1) {
    mma16(c, ah, bh0, bh1);
    mma16(c, ah, bm0, bm1);
    mma16(c, am, bh0, bh1);
    mma16(c, ah, bl0, bl1);
    mma16(c, al, bh0, bh1);
    mma16(c, am, bm0, bm1);
}
__device__ __forceinline__ float epi(float z, float gi_, float gf_, float go_,
                                     float p, float lk, float th) {
    float ig = 1.0f / (1.0f + expf(-gi_));
    float fg = 1.0f / (1.0f + expf(-gf_));
    float og = 1.0f / (1.0f + expf(-go_));
    float s = (1.0f - lk) * (fg * p) + lk * tanhf(ig * z);
    s *= og;
    return (s > th) ? (s - th) : s;
}

__global__ __launch_bounds__(256, 2)
void gser_h3(const float* __restrict__ inputs,
             const float* __restrict__ prev,
             const float* __restrict__ Wres,
             const float* __restrict__ Win,
             const float* __restrict__ Wgate,
             const float* __restrict__ leakp,
             const float* __restrict__ thrp,
             float* __restrict__ out)
{
    const int bx = blockIdx.x;
    const int m0 = blockIdx.y * 64;
    const int n0 = bx * 64;
    const int tid = threadIdx.x;
    const int wid = tid >> 5;
    const int lane = tid & 31;
    const int m0w = (wid & 1) * 32;      // warp grid 2m x 4n, warp tile 32x16
    const int n0w = (wid >> 1) * 16;

    extern __shared__ char smc[];
    const uint32_t sb = smem_u32(smc);
    float* s_lk = reinterpret_cast<float*>(smc + OFF_LK);
    float* s_th = reinterpret_cast<float*>(smc + OFF_TH);

    // zero-fill pad: out[m0:m0+64, 512+bx*64 : +64)
    {
        const float4 z4 = make_float4(0.f, 0.f, 0.f, 0.f);
        #pragma unroll
        for (int it = 0; it < 4; ++it) {
            int idx = tid + 256 * it;
            int r = idx >> 4, q = idx & 15;
            *reinterpret_cast<float4*>(out + (size_t)(m0 + r) * MAXD + ACT + bx * 64 + 4 * q) = z4;
        }
    }
    if (tid < 64) {
        s_lk[tid] = 1.0f / (1.0f + expf(-leakp[n0 + tid]));
        s_th[tid] = log1pf(expf(thrp[n0 + tid]));
    }

    // accumulators: z + 3 gates, warp tile 32x16 => [mi][n8][4]
    float z[2][2][4];
    float g[3][2][2][4];
    #pragma unroll
    for (int a = 0; a < 2; ++a)
        #pragma unroll
        for (int b = 0; b < 2; ++b)
            #pragma unroll
            for (int k = 0; k < 4; ++k) {
                z[a][b][k] = 0.f;
                g[0][a][b][k] = 0.f; g[1][a][b][k] = 0.f; g[2][a][b][k] = 0.f;
            }

    // ldsm lane-address pieces
    const uint32_t aOffA = (uint32_t)((m0w + (lane & 15)) * 144) + ((lane >> 4) << 4);  // phase A, A op
    const uint32_t bRowA = (uint32_t)(((lane & 7) + ((lane >> 3) & 1) * 8) * 144)       // phase A, B op (trans)
                         + (uint32_t)((n0w + ((lane >> 4) << 3)) * 2);
    const uint32_t aOffB = (uint32_t)((m0w + (lane & 15)) * 48) + ((lane >> 4) << 4);   // phase B, A op
    const uint32_t bOffB = (uint32_t)((n0w + (lane & 7) + ((lane >> 4) << 3)) * 48)     // phase B, B op
                         + ((lane & 8) ? 16u : 0u);

    // ================= Phase A: z += prev[:, :512] @ Wres[:512, n0:+64] =================
    for (int c = 0; c < 8; ++c) {
        const int kc = 64 * c;
        __syncthreads();
        // load + split + store (coalesced LDG.64, conflict-free STS.32)
        #pragma unroll
        for (int i = 0; i < 8; ++i) {
            const int r = wid * 8 + i;              // 0..63
            const uint32_t off = (uint32_t)(r * 144 + 4 * lane);
            float2 v = *reinterpret_cast<const float2*>(prev + (size_t)(m0 + r) * MAXD + kc + 2 * lane);
            uint32_t ph, pm, pl;
            split_pair(v.x, v.y, ph, pm, pl);
            *reinterpret_cast<uint32_t*>(smc + PA_PREV(0) + off) = ph;
            *reinterpret_cast<uint32_t*>(smc + PA_PREV(1) + off) = pm;
            *reinterpret_cast<uint32_t*>(smc + PA_PREV(2) + off) = pl;
            float2 w = *reinterpret_cast<const float2*>(Wres + (size_t)(kc + r) * MAXD + n0 + 2 * lane);
            split_pair(w.x, w.y, ph, pm, pl);
            *reinterpret_cast<uint32_t*>(smc + PA_WRES(0) + off) = ph;
            *reinterpret_cast<uint32_t*>(smc + PA_WRES(1) + off) = pm;
            *reinterpret_cast<uint32_t*>(smc + PA_WRES(2) + off) = pl;
        }
        __syncthreads();

        #pragma unroll
        for (int ks = 0; ks < 4; ++ks) {
            uint32_t aF[3][2][4];
            #pragma unroll
            for (int p = 0; p < 3; ++p) {
                ldsm4(aF[p][0], sb + PA_PREV(p) + aOffA + ks * 32);
                ldsm4(aF[p][1], sb + PA_PREV(p) + aOffA + 16 * 144 + ks * 32);
            }
            uint32_t bF[3][4];
            #pragma unroll
            for (int p = 0; p < 3; ++p)
                ldsm4t(bF[p], sb + PA_WRES(p) + bRowA + (uint32_t)(ks * 16 * 144));
            #pragma unroll
            for (int mi = 0; mi < 2; ++mi)
                #pragma unroll
                for (int j = 0; j < 2; ++j)
                    six(z[mi][j], aF[0][mi], aF[1][mi], aF[2][mi],
                        bF[0][2 * j], bF[0][2 * j + 1],
                        bF[1][2 * j], bF[1][2 * j + 1],
                        bF[2][2 * j], bF[2][2 * j + 1]);
        }
    }

    // ================= Phase B: K=128 inputs GEMM (z += in@Win^T; gates) =================
    const float* wmat[4] = {
        Win   + (size_t)n0 * IN_DIM,
        Wgate + (size_t)n0 * IN_DIM,
        Wgate + (size_t)(ACT + n0) * IN_DIM,
        Wgate + (size_t)(2 * ACT + n0) * IN_DIM
    };

    for (int c = 0; c < 8; ++c) {
        const int kc = 16 * c;
        __syncthreads();
        {
            const int r = tid >> 2, k0 = 4 * (tid & 3);
            const uint32_t off = (uint32_t)(r * 48 + 2 * k0);
            float4 v = *reinterpret_cast<const float4*>(inputs + (size_t)(m0 + r) * IN_DIM + kc + k0);
            uint32_t h0, mm0, l0, h1, mm1, l1;
            split_pair(v.x, v.y, h0, mm0, l0);
            split_pair(v.z, v.w, h1, mm1, l1);
            *reinterpret_cast<uint2*>(smc + PB_INP(0) + off) = make_uint2(h0, h1);
            *reinterpret_cast<uint2*>(smc + PB_INP(1) + off) = make_uint2(mm0, mm1);
            *reinterpret_cast<uint2*>(smc + PB_INP(2) + off) = make_uint2(l0, l1);
            #pragma unroll
            for (int mt = 0; mt < 4; ++mt) {
                float4 w = *reinterpret_cast<const float4*>(wmat[mt] + (size_t)r * IN_DIM + kc + k0);
                split_pair(w.x, w.y, h0, mm0, l0);
                split_pair(w.z, w.w, h1, mm1, l1);
                *reinterpret_cast<uint2*>(smc + PB_WM(mt, 0) + off) = make_uint2(h0, h1);
                *reinterpret_cast<uint2*>(smc + PB_WM(mt, 1) + off) = make_uint2(mm0, mm1);
                *reinterpret_cast<uint2*>(smc + PB_WM(mt, 2) + off) = make_uint2(l0, l1);
            }
        }
        __syncthreads();

        uint32_t aF[3][2][4];
        #pragma unroll
        for (int p = 0; p < 3; ++p) {
            ldsm4(aF[p][0], sb + PB_INP(p) + aOffB);
            ldsm4(aF[p][1], sb + PB_INP(p) + aOffB + 16 * 48);
        }
        #pragma unroll
        for (int mt = 0; mt < 4; ++mt) {
            uint32_t bF[3][4];
            #pragma unroll
            for (int p = 0; p < 3; ++p)
                ldsm4(bF[p], sb + PB_WM(mt, p) + bOffB);
            float (*acc)[2][4] = (mt == 0) ? z : g[mt - 1];
            #pragma unroll
            for (int mi = 0; mi < 2; ++mi)
                #pragma unroll
                for (int j = 0; j < 2; ++j)
                    six(acc[mi][j], aF[0][mi], aF[1][mi], aF[2][mi],
                        bF[0][2 * j], bF[0][2 * j + 1],
                        bF[1][2 * j], bF[1][2 * j + 1],
                        bF[2][2 * j], bF[2][2 * j + 1]);
        }
    }

    // ================= Epilogue (warp 32x16; frag rows lane>>2, cols 2*(lane&3)) ====
    const int tq = lane >> 2, tr = lane & 3;
    #pragma unroll
    for (int mi = 0; mi < 2; ++mi) {
        const int mg0 = m0 + m0w + mi * 16 + tq;
        const int mg1 = mg0 + 8;
        #pragma unroll
        for (int ni = 0; ni < 2; ++ni) {
            const int cc = n0w + ni * 8 + 2 * tr;
            const int ng = n0 + cc;
            const float lk0 = s_lk[cc], lk1 = s_lk[cc + 1];
            const float th0 = s_th[cc], th1 = s_th[cc + 1];
            const float2 p0 = *reinterpret_cast<const float2*>(prev + (size_t)mg0 * MAXD + ng);
            const float2 p1 = *reinterpret_cast<const float2*>(prev + (size_t)mg1 * MAXD + ng);
            float2 o0, o1;
            o0.x = epi(z[mi][ni][0], g[0][mi][ni][0], g[1][mi][ni][0], g[2][mi][ni][0], p0.x, lk0, th0);
            o0.y = epi(z[mi][ni][1], g[0][mi][ni][1], g[1][mi][ni][1], g[2][mi][ni][1], p0.y, lk1, th1);
            o1.x = epi(z[mi][ni][2], g[0][mi][ni][2], g[1][mi][ni][2], g[2][mi][ni][2], p1.x, lk0, th0);
            o1.y = epi(z[mi][ni][3], g[0][mi][ni][3], g[1][mi][ni][3], g[2][mi][ni][3], p1.y, lk1, th1);
            *reinterpret_cast<float2*>(out + (size_t)mg0 * MAXD + ng) = o0;
            *reinterpret_cast<float2*>(out + (size_t)mg1 * MAXD + ng) = o1;
        }
    }
}

extern "C" void kernel_launch(void* const* d_in, const int* in_sizes, int n_in,
                              void* d_out, int out_size)
{
    const float* inputs = (const float*)d_in[0];
    const float* prev   = (const float*)d_in[1];
    const float* Wres   = (const float*)d_in[2];
    const float* Win    = (const float*)d_in[3];
    const float* Wgate  = (const float*)d_in[4];
    const float* leakp  = (const float*)d_in[5];
    const float* thrp   = (const float*)d_in[6];
    float* out = (float*)d_out;

    cudaFuncSetAttribute(gser_h3, cudaFuncAttributeMaxDynamicSharedMemorySize, SMEM_BYTES);

    dim3 grid(8, B_SZ / 64);
    gser_h3<<<grid, 256, SMEM_BYTES>>>(inputs, prev, Wres, Win, Wgate, leakp, thrp, out);
}

// round 6
// speedup vs baseline: 1.5937x; 1.3658x over previous
#include <cuda_runtime.h>
#include <cuda_fp16.h>
#include <cstdint>

#define B_SZ   32768
#define IN_DIM 128
#define ACT    512
#define MAXD   1024

// ---- smem byte offsets (union of phase A / phase B regions) ----
// Phase A: prev pieces [64m][72k] fp16 (stride 144B), wres pieces [64k][72n] fp16
#define PA_PREV(p)  ((p) * 9216)
#define PA_WRES(p)  (18432 + (p) * 9216)
// Phase B: inputs pieces [64m][24k] fp16 (stride 48B), weights [mt][p] [64n][24k]
#define PB_INP(p)   ((p) * 3072)
#define PB_WM(mt,p) (6144 + ((mt) * 2 + (p)) * 3072)
#define OFF_LK 36864
#define OFF_TH 37120
#define SMEM_BYTES 37632

__device__ __forceinline__ void ldsm4(uint32_t r[4], uint32_t a) {
    asm volatile("ldmatrix.sync.aligned.m8n8.x4.shared.b16 {%0,%1,%2,%3}, [%4];"
        : "=r"(r[0]), "=r"(r[1]), "=r"(r[2]), "=r"(r[3]) : "r"(a));
}
__device__ __forceinline__ void ldsm4t(uint32_t r[4], uint32_t a) {
    asm volatile("ldmatrix.sync.aligned.m8n8.x4.trans.shared.b16 {%0,%1,%2,%3}, [%4];"
        : "=r"(r[0]), "=r"(r[1]), "=r"(r[2]), "=r"(r[3]) : "r"(a));
}
__device__ __forceinline__ uint32_t smem_u32(const void* p) {
    uint32_t a;
    asm("{ .reg .u64 t; cvta.to.shared.u64 t, %1; cvt.u32.u64 %0, t; }" : "=r"(a) : "l"(p));
    return a;
}
__device__ __forceinline__ void mma16(float c[4], const uint32_t a[4], uint32_t b0, uint32_t b1) {
    asm volatile("mma.sync.aligned.m16n8k16.row.col.f32.f16.f16.f32 "
        "{%0,%1,%2,%3},{%4,%5,%6,%7},{%8,%9},{%0,%1,%2,%3};"
        : "+f"(c[0]), "+f"(c[1]), "+f"(c[2]), "+f"(c[3])
        : "r"(a[0]), "r"(a[1]), "r"(a[2]), "r"(a[3]), "r"(b0), "r"(b1));
}
__device__ __forceinline__ uint32_t packh2(float lo, float hi) {
    uint32_t r;
    asm("cvt.rn.f16x2.f32 %0, %1, %2;" : "=r"(r) : "f"(hi), "f"(lo));
    return r;
}
__device__ __forceinline__ float2 unph2(uint32_t p) {
    __half2 h;
    *reinterpret_cast<uint32_t*>(&h) = p;
    return __half22float2(h);
}
// 2-piece fp16 split of a pair of floats: x = h + m (each fp16, rn) to ~2^-22
__device__ __forceinline__ void split_pair(float x0, float x1, uint32_t& ph, uint32_t& pm) {
    ph = packh2(x0, x1);
    float2 h = unph2(ph);
    pm = packh2(x0 - h.x, x1 - h.y);
}
// 3-term product: acc += (ah+am)*(bh+bm) to ~2^-22
__device__ __forceinline__ void three(float c[4],
                                      const uint32_t ah[4], const uint32_t am[4],
                                      uint32_t bh0, uint32_t bh1, uint32_t bm0, uint32_t bm1) {
    mma16(c, ah, bh0, bh1);
    mma16(c, ah, bm0, bm1);
    mma16(c, am, bh0, bh1);
}
__device__ __forceinline__ float epi(float z, float gi_, float gf_, float go_,
                                     float p, float lk, float th) {
    float ig = 1.0f / (1.0f + expf(-gi_));
    float fg = 1.0f / (1.0f + expf(-gf_));
    float og = 1.0f / (1.0f + expf(-go_));
    float s = (1.0f - lk) * (fg * p) + lk * tanhf(ig * z);
    s *= og;
    return (s > th) ? (s - th) : s;
}

__global__ __launch_bounds__(256, 2)
void gser_h2(const float* __restrict__ inputs,
             const float* __restrict__ prev,
             const float* __restrict__ Wres,
             const float* __restrict__ Win,
             const float* __restrict__ Wgate,
             const float* __restrict__ leakp,
             const float* __restrict__ thrp,
             float* __restrict__ out)
{
    const int bx = blockIdx.x;
    const int m0 = blockIdx.y * 64;
    const int n0 = bx * 64;
    const int tid = threadIdx.x;
    const int wid = tid >> 5;
    const int lane = tid & 31;
    const int m0w = (wid & 1) * 32;      // warp grid 2m x 4n, warp tile 32x16
    const int n0w = (wid >> 1) * 16;

    extern __shared__ char smc[];
    const uint32_t sb = smem_u32(smc);
    float* s_lk = reinterpret_cast<float*>(smc + OFF_LK);
    float* s_th = reinterpret_cast<float*>(smc + OFF_TH);

    // zero-fill pad: out[m0:m0+64, 512+bx*64 : +64)
    {
        const float4 z4 = make_float4(0.f, 0.f, 0.f, 0.f);
        #pragma unroll
        for (int it = 0; it < 4; ++it) {
            int idx = tid + 256 * it;
            int r = idx >> 4, q = idx & 15;
            *reinterpret_cast<float4*>(out + (size_t)(m0 + r) * MAXD + ACT + bx * 64 + 4 * q) = z4;
        }
    }
    if (tid < 64) {
        s_lk[tid] = 1.0f / (1.0f + expf(-leakp[n0 + tid]));
        s_th[tid] = log1pf(expf(thrp[n0 + tid]));
    }

    // accumulators: z + 3 gates, warp tile 32x16 => [mi][n8][4]
    float z[2][2][4];
    float g[3][2][2][4];
    #pragma unroll
    for (int a = 0; a < 2; ++a)
        #pragma unroll
        for (int b = 0; b < 2; ++b)
            #pragma unroll
            for (int k = 0; k < 4; ++k) {
                z[a][b][k] = 0.f;
                g[0][a][b][k] = 0.f; g[1][a][b][k] = 0.f; g[2][a][b][k] = 0.f;
            }

    // ldsm lane-address pieces
    const uint32_t aOffA = (uint32_t)((m0w + (lane & 15)) * 144) + ((lane >> 4) << 4);  // phase A, A op
    const uint32_t bRowA = (uint32_t)(((lane & 7) + ((lane >> 3) & 1) * 8) * 144)       // phase A, B op (trans)
                         + (uint32_t)((n0w + ((lane >> 4) << 3)) * 2);
    const uint32_t aOffB = (uint32_t)((m0w + (lane & 15)) * 48) + ((lane >> 4) << 4);   // phase B, A op
    const uint32_t bOffB = (uint32_t)((n0w + (lane & 7) + ((lane >> 4) << 3)) * 48)     // phase B, B op
                         + ((lane & 8) ? 16u : 0u);

    // ================= Phase A: z += prev[:, :512] @ Wres[:512, n0:+64] =================
    for (int c = 0; c < 8; ++c) {
        const int kc = 64 * c;
        __syncthreads();
        #pragma unroll
        for (int i = 0; i < 8; ++i) {
            const int r = wid * 8 + i;              // 0..63
            const uint32_t off = (uint32_t)(r * 144 + 4 * lane);
            float2 v = *reinterpret_cast<const float2*>(prev + (size_t)(m0 + r) * MAXD + kc + 2 * lane);
            uint32_t ph, pm;
            split_pair(v.x, v.y, ph, pm);
            *reinterpret_cast<uint32_t*>(smc + PA_PREV(0) + off) = ph;
            *reinterpret_cast<uint32_t*>(smc + PA_PREV(1) + off) = pm;
            float2 w = *reinterpret_cast<const float2*>(Wres + (size_t)(kc + r) * MAXD + n0 + 2 * lane);
            split_pair(w.x, w.y, ph, pm);
            *reinterpret_cast<uint32_t*>(smc + PA_WRES(0) + off) = ph;
            *reinterpret_cast<uint32_t*>(smc + PA_WRES(1) + off) = pm;
        }
        __syncthreads();

        #pragma unroll
        for (int ks = 0; ks < 4; ++ks) {
            uint32_t aF[2][2][4];
            #pragma unroll
            for (int p = 0; p < 2; ++p) {
                ldsm4(aF[p][0], sb + PA_PREV(p) + aOffA + ks * 32);
                ldsm4(aF[p][1], sb + PA_PREV(p) + aOffA + 16 * 144 + ks * 32);
            }
            uint32_t bF[2][4];
            #pragma unroll
            for (int p = 0; p < 2; ++p)
                ldsm4t(bF[p], sb + PA_WRES(p) + bRowA + (uint32_t)(ks * 16 * 144));
            #pragma unroll
            for (int mi = 0; mi < 2; ++mi)
                #pragma unroll
                for (int j = 0; j < 2; ++j)
                    three(z[mi][j], aF[0][mi], aF[1][mi],
                          bF[0][2 * j], bF[0][2 * j + 1],
                          bF[1][2 * j], bF[1][2 * j + 1]);
        }
    }

    // ================= Phase B: K=128 inputs GEMM (z += in@Win^T; gates) =================
    const float* wmat[4] = {
        Win   + (size_t)n0 * IN_DIM,
        Wgate + (size_t)n0 * IN_DIM,
        Wgate + (size_t)(ACT + n0) * IN_DIM,
        Wgate + (size_t)(2 * ACT + n0) * IN_DIM
    };

    for (int c = 0; c < 8; ++c) {
        const int kc = 16 * c;
        __syncthreads();
        {
            const int r = tid >> 2, k0 = 4 * (tid & 3);
            const uint32_t off = (uint32_t)(r * 48 + 2 * k0);
            float4 v = *reinterpret_cast<const float4*>(inputs + (size_t)(m0 + r) * IN_DIM + kc + k0);
            uint32_t h0, m0p, h1, m1p;
            split_pair(v.x, v.y, h0, m0p);
            split_pair(v.z, v.w, h1, m1p);
            *reinterpret_cast<uint2*>(smc + PB_INP(0) + off) = make_uint2(h0, h1);
            *reinterpret_cast<uint2*>(smc + PB_INP(1) + off) = make_uint2(m0p, m1p);
            #pragma unroll
            for (int mt = 0; mt < 4; ++mt) {
                float4 w = *reinterpret_cast<const float4*>(wmat[mt] + (size_t)r * IN_DIM + kc + k0);
                split_pair(w.x, w.y, h0, m0p);
                split_pair(w.z, w.w, h1, m1p);
                *reinterpret_cast<uint2*>(smc + PB_WM(mt, 0) + off) = make_uint2(h0, h1);
                *reinterpret_cast<uint2*>(smc + PB_WM(mt, 1) + off) = make_uint2(m0p, m1p);
            }
        }
        __syncthreads();

        uint32_t aF[2][2][4];
        #pragma unroll
        for (int p = 0; p < 2; ++p) {
            ldsm4(aF[p][0], sb + PB_INP(p) + aOffB);
            ldsm4(aF[p][1], sb + PB_INP(p) + aOffB + 16 * 48);
        }
        #pragma unroll
        for (int mt = 0; mt < 4; ++mt) {
            uint32_t bF[2][4];
            #pragma unroll
            for (int p = 0; p < 2; ++p)
                ldsm4(bF[p], sb + PB_WM(mt, p) + bOffB);
            float (*acc)[2][4] = (mt == 0) ? z : g[mt - 1];
            #pragma unroll
            for (int mi = 0; mi < 2; ++mi)
                #pragma unroll
                for (int j = 0; j < 2; ++j)
                    three(acc[mi][j], aF[0][mi], aF[1][mi],
                          bF[0][2 * j], bF[0][2 * j + 1],
                          bF[1][2 * j], bF[1][2 * j + 1]);
        }
    }

    // ================= Epilogue (warp 32x16; frag rows lane>>2, cols 2*(lane&3)) ====
    const int tq = lane >> 2, tr = lane & 3;
    #pragma unroll
    for (int mi = 0; mi < 2; ++mi) {
        const int mg0 = m0 + m0w + mi * 16 + tq;
        const int mg1 = mg0 + 8;
        #pragma unroll
        for (int ni = 0; ni < 2; ++ni) {
            const int cc = n0w + ni * 8 + 2 * tr;
            const int ng = n0 + cc;
            const float lk0 = s_lk[cc], lk1 = s_lk[cc + 1];
            const float th0 = s_th[cc], th1 = s_th[cc + 1];
            const float2 p0 = *reinterpret_cast<const float2*>(prev + (size_t)mg0 * MAXD + ng);
            const float2 p1 = *reinterpret_cast<const float2*>(prev + (size_t)mg1 * MAXD + ng);
            float2 o0, o1;
            o0.x = epi(z[mi][ni][0], g[0][mi][ni][0], g[1][mi][ni][0], g[2][mi][ni][0], p0.x, lk0, th0);
            o0.y = epi(z[mi][ni][1], g[0][mi][ni][1], g[1][mi][ni][1], g[2][mi][ni][1], p0.y, lk1, th1);
            o1.x = epi(z[mi][ni][2], g[0][mi][ni][2], g[1][mi][ni][2], g[2][mi][ni][2], p1.x, lk0, th0);
            o1.y = epi(z[mi][ni][3], g[0][mi][ni][3], g[1][mi][ni][3], g[2][mi][ni][3], p1.y, lk1, th1);
            *reinterpret_cast<float2*>(out + (size_t)mg0 * MAXD + ng) = o0;
            *reinterpret_cast<float2*>(out + (size_t)mg1 * MAXD + ng) = o1;
        }
    }
}

extern "C" void kernel_launch(void* const* d_in, const int* in_sizes, int n_in,
                              void* d_out, int out_size)
{
    const float* inputs = (const float*)d_in[0];
    const float* prev   = (const float*)d_in[1];
    const float* Wres   = (const float*)d_in[2];
    const float* Win    = (const float*)d_in[3];
    const float* Wgate  = (const float*)d_in[4];
    const float* leakp  = (const float*)d_in[5];
    const float* thrp   = (const float*)d_in[6];
    float* out = (float*)d_out;

    cudaFuncSetAttribute(gser_h2, cudaFuncAttributeMaxDynamicSharedMemorySize, SMEM_BYTES);

    dim3 grid(8, B_SZ / 64);
    gser_h2<<<grid, 256, SMEM_BYTES>>>(inputs, prev, Wres, Win, Wgate, leakp, thrp, out);
}

// round 7
// speedup vs baseline: 1.7792x; 1.1164x over previous
#include <cuda_runtime.h>
#include <cuda_fp16.h>
#include <cstdint>

#define B_SZ   32768
#define IN_DIM 128
#define ACT    512
#define MAXD   1024

// ---- smem byte offsets ----
// Region0 (phase-A tiles / phase-B tiles union):
//  phase A: A-part (prev or inputs) [128 rows][64k fp16, stride 144B] per piece
//           B-part (Wres [64k][64n] or Win [64n][64k]) [64][144B] per piece
//  phase B: inputs [128][32k fp16, stride 80B]; weights 3 mats [32n][32k, stride 80B]
#define PA_A(p)    ((p) * 18432)
#define PA_B(p)    (36864 + (p) * 9216)
#define PB_INP(p)  ((p) * 10240)
#define PB_W(mt,p) (20480 + ((mt) * 2 + (p)) * 2560)
#define ZPARK      55296          // fp32 [128 rows][stride 72 floats] = 36864B
#define OFF_LK     92160
#define OFF_TH     92416
#define SMEM_BYTES 92672

__device__ __forceinline__ void ldsm4(uint32_t r[4], uint32_t a) {
    asm volatile("ldmatrix.sync.aligned.m8n8.x4.shared.b16 {%0,%1,%2,%3}, [%4];"
        : "=r"(r[0]), "=r"(r[1]), "=r"(r[2]), "=r"(r[3]) : "r"(a));
}
__device__ __forceinline__ void ldsm4t(uint32_t r[4], uint32_t a) {
    asm volatile("ldmatrix.sync.aligned.m8n8.x4.trans.shared.b16 {%0,%1,%2,%3}, [%4];"
        : "=r"(r[0]), "=r"(r[1]), "=r"(r[2]), "=r"(r[3]) : "r"(a));
}
__device__ __forceinline__ uint32_t smem_u32(const void* p) {
    uint32_t a;
    asm("{ .reg .u64 t; cvta.to.shared.u64 t, %1; cvt.u32.u64 %0, t; }" : "=r"(a) : "l"(p));
    return a;
}
__device__ __forceinline__ void mma16(float c[4], const uint32_t a[4], uint32_t b0, uint32_t b1) {
    asm volatile("mma.sync.aligned.m16n8k16.row.col.f32.f16.f16.f32 "
        "{%0,%1,%2,%3},{%4,%5,%6,%7},{%8,%9},{%0,%1,%2,%3};"
        : "+f"(c[0]), "+f"(c[1]), "+f"(c[2]), "+f"(c[3])
        : "r"(a[0]), "r"(a[1]), "r"(a[2]), "r"(a[3]), "r"(b0), "r"(b1));
}
__device__ __forceinline__ uint32_t packh2(float lo, float hi) {
    uint32_t r;
    asm("cvt.rn.f16x2.f32 %0, %1, %2;" : "=r"(r) : "f"(hi), "f"(lo));
    return r;
}
__device__ __forceinline__ float2 unph2(uint32_t p) {
    __half2 h;
    *reinterpret_cast<uint32_t*>(&h) = p;
    return __half22float2(h);
}
__device__ __forceinline__ void split_pair(float x0, float x1, uint32_t& ph, uint32_t& pm) {
    ph = packh2(x0, x1);
    float2 h = unph2(ph);
    pm = packh2(x0 - h.x, x1 - h.y);
}
__device__ __forceinline__ void three(float c[4],
                                      const uint32_t ah[4], const uint32_t am[4],
                                      uint32_t bh0, uint32_t bh1, uint32_t bm0, uint32_t bm1) {
    mma16(c, ah, bh0, bh1);
    mma16(c, ah, bm0, bm1);
    mma16(c, am, bh0, bh1);
}
__device__ __forceinline__ float epi(float z, float gi_, float gf_, float go_,
                                     float p, float lk, float th) {
    float ig = 1.0f / (1.0f + expf(-gi_));
    float fg = 1.0f / (1.0f + expf(-gf_));
    float og = 1.0f / (1.0f + expf(-go_));
    float s = (1.0f - lk) * (fg * p) + lk * tanhf(ig * z);
    s *= og;
    return (s > th) ? (s - th) : s;
}

__global__ __launch_bounds__(256, 2)
void gser_p2(const float* __restrict__ inputs,
             const float* __restrict__ prev,
             const float* __restrict__ Wres,
             const float* __restrict__ Win,
             const float* __restrict__ Wgate,
             const float* __restrict__ leakp,
             const float* __restrict__ thrp,
             float* __restrict__ out)
{
    const int bx = blockIdx.x;
    const int m0 = blockIdx.y * 128;
    const int n0 = bx * 64;
    const int tid = threadIdx.x;
    const int wid = tid >> 5;
    const int lane = tid & 31;
    // phase A warp grid: 4m x 2n, tiles 32x32
    const int m0A = (wid & 3) * 32;
    const int n0A = (wid >> 2) * 32;
    // phase B warp grid: 4m x 2n, tiles 32x16
    const int n0B = (wid >> 2) * 16;

    extern __shared__ char smc[];
    const uint32_t sb = smem_u32(smc);
    float* s_lk = reinterpret_cast<float*>(smc + OFF_LK);
    float* s_th = reinterpret_cast<float*>(smc + OFF_TH);
    float* s_z  = reinterpret_cast<float*>(smc + ZPARK);

    // zero-fill pad: out[m0:m0+128, 512+bx*64 : +64)
    {
        const float4 z4 = make_float4(0.f, 0.f, 0.f, 0.f);
        #pragma unroll
        for (int it = 0; it < 8; ++it) {
            int idx = tid + 256 * it;
            int r = idx >> 4, q = idx & 15;
            *reinterpret_cast<float4*>(out + (size_t)(m0 + r) * MAXD + ACT + bx * 64 + 4 * q) = z4;
        }
    }
    if (tid < 64) {
        s_lk[tid] = 1.0f / (1.0f + expf(-leakp[n0 + tid]));
        s_th[tid] = log1pf(expf(thrp[n0 + tid]));
    }

    // ldsm lane-address pieces
    const uint32_t aOffA  = (uint32_t)((m0A + (lane & 15)) * 144) + ((lane >> 4) << 4);
    const uint32_t bTrans = (uint32_t)(((lane & 7) + ((lane >> 3) & 1) * 8) * 144)
                          + (uint32_t)((n0A + ((lane >> 4) << 3)) * 2);
    const uint32_t bWin   = (uint32_t)((n0A + (lane & 7) + ((lane >> 4) << 3)) * 144)
                          + ((lane & 8) ? 16u : 0u);
    const uint32_t aOffB  = (uint32_t)((m0A + (lane & 15)) * 80) + ((lane >> 4) << 4);
    const uint32_t bOffB  = (uint32_t)((n0B + (lane & 7) + ((lane >> 4) << 3)) * 80)
                          + ((lane & 8) ? 16u : 0u);

    // ================= Phase A: z = prev@Wres + inputs@Win^T (32x32 warp tiles) =====
    float z[2][4][4];
    #pragma unroll
    for (int a = 0; a < 2; ++a)
        #pragma unroll
        for (int b = 0; b < 4; ++b)
            #pragma unroll
            for (int k = 0; k < 4; ++k) z[a][b][k] = 0.f;

    for (int c = 0; c < 10; ++c) {
        __syncthreads();
        if (c < 8) {
            const int kc = 64 * c;
            // prev tile [128m][64k]
            #pragma unroll
            for (int i = 0; i < 16; ++i) {
                const int r = wid * 16 + i;
                const uint32_t off = (uint32_t)(r * 144 + 4 * lane);
                float2 v = *reinterpret_cast<const float2*>(prev + (size_t)(m0 + r) * MAXD + kc + 2 * lane);
                uint32_t ph, pm;
                split_pair(v.x, v.y, ph, pm);
                *reinterpret_cast<uint32_t*>(smc + PA_A(0) + off) = ph;
                *reinterpret_cast<uint32_t*>(smc + PA_A(1) + off) = pm;
            }
            // wres tile [64k][64n]
            #pragma unroll
            for (int i = 0; i < 8; ++i) {
                const int r = wid * 8 + i;
                const uint32_t off = (uint32_t)(r * 144 + 4 * lane);
                float2 w = *reinterpret_cast<const float2*>(Wres + (size_t)(kc + r) * MAXD + n0 + 2 * lane);
                uint32_t ph, pm;
                split_pair(w.x, w.y, ph, pm);
                *reinterpret_cast<uint32_t*>(smc + PA_B(0) + off) = ph;
                *reinterpret_cast<uint32_t*>(smc + PA_B(1) + off) = pm;
            }
        } else {
            const int kc = 64 * (c - 8);
            // inputs tile [128m][64k]
            #pragma unroll
            for (int i = 0; i < 16; ++i) {
                const int r = wid * 16 + i;
                const uint32_t off = (uint32_t)(r * 144 + 4 * lane);
                float2 v = *reinterpret_cast<const float2*>(inputs + (size_t)(m0 + r) * IN_DIM + kc + 2 * lane);
                uint32_t ph, pm;
                split_pair(v.x, v.y, ph, pm);
                *reinterpret_cast<uint32_t*>(smc + PA_A(0) + off) = ph;
                *reinterpret_cast<uint32_t*>(smc + PA_A(1) + off) = pm;
            }
            // Win tile [64n][64k]
            #pragma unroll
            for (int i = 0; i < 8; ++i) {
                const int r = wid * 8 + i;
                const uint32_t off = (uint32_t)(r * 144 + 4 * lane);
                float2 w = *reinterpret_cast<const float2*>(Win + (size_t)(n0 + r) * IN_DIM + kc + 2 * lane);
                uint32_t ph, pm;
                split_pair(w.x, w.y, ph, pm);
                *reinterpret_cast<uint32_t*>(smc + PA_B(0) + off) = ph;
                *reinterpret_cast<uint32_t*>(smc + PA_B(1) + off) = pm;
            }
        }
        __syncthreads();

        const bool trans = (c < 8);
        #pragma unroll
        for (int ks = 0; ks < 4; ++ks) {
            uint32_t aF[2][2][4];
            #pragma unroll
            for (int p = 0; p < 2; ++p) {
                ldsm4(aF[p][0], sb + PA_A(p) + aOffA + ks * 32);
                ldsm4(aF[p][1], sb + PA_A(p) + aOffA + 16 * 144 + ks * 32);
            }
            uint32_t bF[2][2][4];
            if (trans) {
                #pragma unroll
                for (int p = 0; p < 2; ++p)
                    #pragma unroll
                    for (int j = 0; j < 2; ++j)
                        ldsm4t(bF[p][j], sb + PA_B(p) + bTrans + (uint32_t)(ks * 16 * 144) + j * 32);
            } else {
                #pragma unroll
                for (int p = 0; p < 2; ++p)
                    #pragma unroll
                    for (int j = 0; j < 2; ++j)
                        ldsm4(bF[p][j], sb + PA_B(p) + bWin + (uint32_t)(j * 16 * 144) + ks * 32);
            }
            #pragma unroll
            for (int mi = 0; mi < 2; ++mi)
                #pragma unroll
                for (int j = 0; j < 2; ++j) {
                    three(z[mi][2 * j],     aF[0][mi], aF[1][mi],
                          bF[0][j][0], bF[0][j][1], bF[1][j][0], bF[1][j][1]);
                    three(z[mi][2 * j + 1], aF[0][mi], aF[1][mi],
                          bF[0][j][2], bF[0][j][3], bF[1][j][2], bF[1][j][3]);
                }
        }
    }

    // ---- park z to smem [128][72 floats] ----
    {
        const int tq = lane >> 2, tr = lane & 3;
        #pragma unroll
        for (int mi = 0; mi < 2; ++mi) {
            const int r0 = m0A + mi * 16 + tq;
            #pragma unroll
            for (int j = 0; j < 4; ++j) {
                const int cc = n0A + j * 8 + 2 * tr;
                *reinterpret_cast<float2*>(s_z + (size_t)r0 * 72 + cc)       = make_float2(z[mi][j][0], z[mi][j][1]);
                *reinterpret_cast<float2*>(s_z + (size_t)(r0 + 8) * 72 + cc) = make_float2(z[mi][j][2], z[mi][j][3]);
            }
        }
    }

    // ================= Phase B: gates (3 mats), two 32-col halves =================
    for (int h = 0; h < 2; ++h) {
        float g[3][2][2][4];
        #pragma unroll
        for (int a = 0; a < 3; ++a)
            #pragma unroll
            for (int b = 0; b < 2; ++b)
                #pragma unroll
                for (int j = 0; j < 2; ++j)
                    #pragma unroll
                    for (int k = 0; k < 4; ++k) g[a][b][j][k] = 0.f;

        for (int c = 0; c < 4; ++c) {
            const int kc = 32 * c;
            __syncthreads();
            // inputs [128m][32k]
            #pragma unroll
            for (int it = 0; it < 4; ++it) {
                int idx = tid + 256 * it;
                int r = idx >> 3, q = idx & 7;
                float4 v = *reinterpret_cast<const float4*>(inputs + (size_t)(m0 + r) * IN_DIM + kc + 4 * q);
                uint32_t h0, mm0, h1, mm1;
                split_pair(v.x, v.y, h0, mm0);
                split_pair(v.z, v.w, h1, mm1);
                *reinterpret_cast<uint2*>(smc + PB_INP(0) + r * 80 + q * 8) = make_uint2(h0, h1);
                *reinterpret_cast<uint2*>(smc + PB_INP(1) + r * 80 + q * 8) = make_uint2(mm0, mm1);
            }
            // weights: 3 mats [32n][32k], rows = gate cols (n0 + 32h + r)
            {
                int r = tid >> 3, q = tid & 7;
                #pragma unroll
                for (int mt = 0; mt < 3; ++mt) {
                    const float* W = Wgate + (size_t)(mt * ACT + n0 + 32 * h + r) * IN_DIM + kc + 4 * q;
                    float4 w = *reinterpret_cast<const float4*>(W);
                    uint32_t h0, mm0, h1, mm1;
                    split_pair(w.x, w.y, h0, mm0);
                    split_pair(w.z, w.w, h1, mm1);
                    *reinterpret_cast<uint2*>(smc + PB_W(mt, 0) + r * 80 + q * 8) = make_uint2(h0, h1);
                    *reinterpret_cast<uint2*>(smc + PB_W(mt, 1) + r * 80 + q * 8) = make_uint2(mm0, mm1);
                }
            }
            __syncthreads();

            #pragma unroll
            for (int ks = 0; ks < 2; ++ks) {
                uint32_t aF[2][2][4];
                #pragma unroll
                for (int p = 0; p < 2; ++p) {
                    ldsm4(aF[p][0], sb + PB_INP(p) + aOffB + ks * 32);
                    ldsm4(aF[p][1], sb + PB_INP(p) + aOffB + 16 * 80 + ks * 32);
                }
                #pragma unroll
                for (int mt = 0; mt < 3; ++mt) {
                    uint32_t bF[2][4];
                    #pragma unroll
                    for (int p = 0; p < 2; ++p)
                        ldsm4(bF[p], sb + PB_W(mt, p) + bOffB + ks * 32);
                    #pragma unroll
                    for (int mi = 0; mi < 2; ++mi) {
                        three(g[mt][mi][0], aF[0][mi], aF[1][mi], bF[0][0], bF[0][1], bF[1][0], bF[1][1]);
                        three(g[mt][mi][1], aF[0][mi], aF[1][mi], bF[0][2], bF[0][3], bF[1][2], bF[1][3]);
                    }
                }
            }
        }

        // ---- epilogue for this half ----
        const int tq = lane >> 2, tr = lane & 3;
        #pragma unroll
        for (int mi = 0; mi < 2; ++mi) {
            const int rr0 = m0A + mi * 16 + tq;       // CTA-relative row
            const int mg0 = m0 + rr0;
            const int mg1 = mg0 + 8;
            #pragma unroll
            for (int ni = 0; ni < 2; ++ni) {
                const int cc = 32 * h + n0B + ni * 8 + 2 * tr;   // CTA-relative col
                const int ng = n0 + cc;
                const float lk0 = s_lk[cc], lk1 = s_lk[cc + 1];
                const float th0 = s_th[cc], th1 = s_th[cc + 1];
                const float2 z0 = *reinterpret_cast<const float2*>(s_z + (size_t)rr0 * 72 + cc);
                const float2 z1 = *reinterpret_cast<const float2*>(s_z + (size_t)(rr0 + 8) * 72 + cc);
                const float2 p0 = *reinterpret_cast<const float2*>(prev + (size_t)mg0 * MAXD + ng);
                const float2 p1 = *reinterpret_cast<const float2*>(prev + (size_t)mg1 * MAXD + ng);
                float2 o0, o1;
                o0.x = epi(z0.x, g[0][mi][ni][0], g[1][mi][ni][0], g[2][mi][ni][0], p0.x, lk0, th0);
                o0.y = epi(z0.y, g[0][mi][ni][1], g[1][mi][ni][1], g[2][mi][ni][1], p0.y, lk1, th1);
                o1.x = epi(z1.x, g[0][mi][ni][2], g[1][mi][ni][2], g[2][mi][ni][2], p1.x, lk0, th0);
                o1.y = epi(z1.y, g[0][mi][ni][3], g[1][mi][ni][3], g[2][mi][ni][3], p1.y, lk1, th1);
                *reinterpret_cast<float2*>(out + (size_t)mg0 * MAXD + ng) = o0;
                *reinterpret_cast<float2*>(out + (size_t)mg1 * MAXD + ng) = o1;
            }
        }
    }
}

extern "C" void kernel_launch(void* const* d_in, const int* in_sizes, int n_in,
                              void* d_out, int out_size)
{
    const float* inputs = (const float*)d_in[0];
    const float* prev   = (const float*)d_in[1];
    const float* Wres   = (const float*)d_in[2];
    const float* Win    = (const float*)d_in[3];
    const float* Wgate  = (const float*)d_in[4];
    const float* leakp  = (const float*)d_in[5];
    const float* thrp   = (const float*)d_in[6];
    float* out = (float*)d_out;

    cudaFuncSetAttribute(gser_p2, cudaFuncAttributeMaxDynamicSharedMemorySize, SMEM_BYTES);

    dim3 grid(8, B_SZ / 128);
    gser_p2<<<grid, 256, SMEM_BYTES>>>(inputs, prev, Wres, Win, Wgate, leakp, thrp, out);
}